// round 11
// baseline (speedup 1.0000x reference)
#include <cuda_runtime.h>
#include <cuda_bf16.h>
#include <math.h>
#include <stdint.h>

#define BDIM 256
#define SDIM 1024
#define DDIM 32
#define KDIM 512
// D * (log(STD) + 0.5*log(2*pi)) with STD=1, D=32  -> 16*log(2*pi)
#define LOG_NORM 29.406033062549525f
#define L2E 1.4426950408889634f

// Scratch (device globals; no allocation allowed)
__device__ float g_w[BDIM * KDIM];   // w[b,k] = exp(c[b,k])
__device__ float g_maxc[BDIM];       // max_k c[b,k]
__device__ float g_maxmu;            // max_k ||mu_k||
// means in mma.sync B-fragment order: [ntile(64)][kstep(2)][lane(32)] -> uint2{b0,b1}
__device__ uint2 g_bfrag[64 * 2 * 32];

__device__ __forceinline__ float ex2f(float a) {
    float r;
    asm("ex2.approx.ftz.f32 %0, %1;" : "=f"(r) : "f"(a));
    return r;
}

__device__ __forceinline__ uint32_t pack_bf16x2(float lo, float hi) {
    uint32_t l = (uint32_t)__bfloat16_as_ushort(__float2bfloat16_rn(lo));
    uint32_t h = (uint32_t)__bfloat16_as_ushort(__float2bfloat16_rn(hi));
    return (h << 16) | l;
}

// m16n8k16 bf16 MMA, f32 accumulate (sm_80+ PTX; no sm_103a-only features)
__device__ __forceinline__ void mma16816(float& c0, float& c1, float& c2, float& c3,
                                         uint32_t a0, uint32_t a1, uint32_t a2, uint32_t a3,
                                         uint32_t b0, uint32_t b1) {
    asm volatile(
        "mma.sync.aligned.m16n8k16.row.col.f32.bf16.bf16.f32 "
        "{%0,%1,%2,%3}, {%4,%5,%6,%7}, {%8,%9}, {%0,%1,%2,%3};"
        : "+f"(c0), "+f"(c1), "+f"(c2), "+f"(c3)
        : "r"(a0), "r"(a1), "r"(a2), "r"(a3), "r"(b0), "r"(b1));
}

__device__ __forceinline__ float warp_max(float v) {
    #pragma unroll
    for (int o = 16; o > 0; o >>= 1) v = fmaxf(v, __shfl_xor_sync(0xFFFFFFFFu, v, o));
    return v;
}
__device__ __forceinline__ float warp_sum(float v) {
    #pragma unroll
    for (int o = 16; o > 0; o >>= 1) v += __shfl_xor_sync(0xFFFFFFFFu, v, o);
    return v;
}

// ---------------------------------------------------------------------------
// Kernel A: per-batch preprocessing with warp-shuffle reductions.
// Grid = B blocks, 512 threads (one per k). Blocks 0-15 also build the
// means B-fragment table (independent work; no extra syncs).
// ---------------------------------------------------------------------------
__global__ void prep_kernel(const float* __restrict__ logits,
                            const float* __restrict__ means) {
    __shared__ float red[16];
    __shared__ float bcast;
    const int b = blockIdx.x;
    const int k = threadIdx.x;
    const int wid = k >> 5;
    const int lane = k & 31;

    // ---- folded frag build (blocks 0..15, threads 0..255) ----
    if (blockIdx.x < 16 && k < 256) {
        const int e = blockIdx.x * 256 + k;         // 0..4095
        const int l = e & 31;
        const int s = (e >> 5) & 1;
        const int j = e >> 6;
        const int n = j * 8 + (l >> 2);
        const int kk = s * 16 + (l & 3) * 2;
        const float* mp = means + n * DDIM + kk;
        uint2 f;
        f.x = pack_bf16x2(mp[0], mp[1]);
        f.y = pack_bf16x2(mp[8], mp[9]);
        g_bfrag[e] = f;
    }

    const float lg = logits[b * KDIM + k];

    // ---- max of logits ----
    float v = warp_max(lg);
    if (lane == 0) red[wid] = v;
    __syncthreads();
    if (k == 0) {
        float m = red[0];
        #pragma unroll
        for (int i = 1; i < 16; i++) m = fmaxf(m, red[i]);
        bcast = m;
    }
    __syncthreads();
    const float maxl = bcast;
    __syncthreads();

    // ---- sum of exp ----
    v = warp_sum(__expf(lg - maxl));
    if (lane == 0) red[wid] = v;
    __syncthreads();
    if (k == 0) {
        float s = red[0];
        #pragma unroll
        for (int i = 1; i < 16; i++) s += red[i];
        bcast = maxl + logf(s);
    }
    __syncthreads();
    const float lse = bcast;
    __syncthreads();

    // ---- m2[k] ----
    const float4* mr = (const float4*)(means + (size_t)k * DDIM);
    float m2 = 0.0f;
    #pragma unroll
    for (int i = 0; i < DDIM / 4; i++) {
        float4 q = mr[i];
        m2 += q.x * q.x + q.y * q.y + q.z * q.z + q.w * q.w;
    }

    const float c = lg - lse - 0.5f * m2 - LOG_NORM;
    g_w[b * KDIM + k] = expf(c);

    // ---- max of c ----
    v = warp_max(c);
    if (lane == 0) red[wid] = v;
    __syncthreads();
    if (k == 0) {
        float m = red[0];
        #pragma unroll
        for (int i = 1; i < 16; i++) m = fmaxf(m, red[i]);
        g_maxc[b] = m;
    }
    __syncthreads();

    // ---- max of m2 -> maxmu (same value from every block; benign) ----
    v = warp_max(m2);
    if (lane == 0) red[wid] = v;
    __syncthreads();
    if (k == 0) {
        float m = red[0];
        #pragma unroll
        for (int i = 1; i < 16; i++) m = fmaxf(m, red[i]);
        g_maxmu = sqrtf(m);
    }
}

// ---------------------------------------------------------------------------
// Kernel B: mma.sync GEMM + fused logsumexp epilogue.
// CTA = 4 s-tiles (512 rows) of one b; prologue (w + B-fragments) amortized.
// Grid = B * 2 = 512 CTAs, 256 threads. Warp w owns rows w*16.., all K.
// ---------------------------------------------------------------------------
#define PITCH 36    // bf16 elems per staged x row (72 B) -> conflict-dodging pitch
#define TILES 4

__global__ __launch_bounds__(256) void nll_hmma(const float* __restrict__ x,
                                                float* __restrict__ out) {
    __shared__ float s_w[KDIM];                     // 2 KB
    __shared__ float s_M[128];
    __shared__ float s_x2[128];
    __shared__ __nv_bfloat16 s_xbf[128 * PITCH];    // 9216 B
    __shared__ uint2 s_bf[64 * 2 * 32];             // 32 KB

    const int tid = threadIdx.x;
    const int wid = tid >> 5;
    const int lane = tid & 31;
    const int b = blockIdx.x >> 1;
    const int halfsel = blockIdx.x & 1;             // tiles halfsel*4 .. +3

    // ---- prologue (once per CTA) ----
    s_w[tid]       = g_w[b * KDIM + tid];
    s_w[tid + 256] = g_w[b * KDIM + tid + 256];
    {
        const uint4* src = (const uint4*)g_bfrag;   // 2048 uint4
        uint4* dst = (uint4*)s_bf;
        #pragma unroll
        for (int i = 0; i < 8; i++) dst[tid + i * 256] = src[tid + i * 256];
    }
    const float maxc = g_maxc[b];
    const float maxmu = g_maxmu;

    const int r0 = wid * 16 + (lane >> 2);
    const int kq = (lane & 3) * 2;

    #pragma unroll 1
    for (int t = 0; t < TILES; t++) {
        const int tile = halfsel * TILES + t;
        __syncthreads();                            // s_xbf free (and prologue visible)

        if (tid < 128) {
            const float4* xr =
                (const float4*)(x + ((size_t)b * SDIM + tile * 128 + tid) * DDIM);
            float x2 = 0.0f;
            #pragma unroll
            for (int i = 0; i < 8; i++) {
                float4 vv = xr[i];
                x2 += vv.x * vv.x + vv.y * vv.y + vv.z * vv.z + vv.w * vv.w;
                uint32_t p0 = pack_bf16x2(vv.x, vv.y);
                uint32_t p1 = pack_bf16x2(vv.z, vv.w);
                uint32_t* dp = (uint32_t*)&s_xbf[tid * PITCH + i * 4];
                dp[0] = p0;
                dp[1] = p1;
            }
            s_x2[tid] = x2;
            s_M[tid] = maxc + sqrtf(x2) * maxmu;
        }
        __syncthreads();

        // ---- A fragments: rows r0, r0+8, 2 k-steps ----
        uint32_t a[8];
        #pragma unroll
        for (int s = 0; s < 2; s++) {
            const int kb = s * 16 + kq;
            a[s * 4 + 0] = *(const uint32_t*)&s_xbf[r0 * PITCH + kb];
            a[s * 4 + 1] = *(const uint32_t*)&s_xbf[(r0 + 8) * PITCH + kb];
            a[s * 4 + 2] = *(const uint32_t*)&s_xbf[r0 * PITCH + kb + 8];
            a[s * 4 + 3] = *(const uint32_t*)&s_xbf[(r0 + 8) * PITCH + kb + 8];
        }

        const float M0 = s_M[r0];
        const float M1 = s_M[r0 + 8];
        const float nM0 = -M0 * L2E;
        const float nM1 = -M1 * L2E;
        float acc0 = 0.0f, acc1 = 0.0f;

        #pragma unroll 4
        for (int j = 0; j < 64; j++) {
            const uint2 bf0 = s_bf[(j * 2 + 0) * 32 + lane];
            const uint2 bf1 = s_bf[(j * 2 + 1) * 32 + lane];
            float c0 = 0.0f, c1 = 0.0f, c2 = 0.0f, c3 = 0.0f;
            mma16816(c0, c1, c2, c3, a[0], a[1], a[2], a[3], bf0.x, bf0.y);
            mma16816(c0, c1, c2, c3, a[4], a[5], a[6], a[7], bf1.x, bf1.y);
            const float2 wv = *(const float2*)&s_w[j * 8 + kq];
            acc0 = fmaf(wv.x, ex2f(fmaf(c0, L2E, nM0)), acc0);
            acc0 = fmaf(wv.y, ex2f(fmaf(c1, L2E, nM0)), acc0);
            acc1 = fmaf(wv.x, ex2f(fmaf(c2, L2E, nM1)), acc1);
            acc1 = fmaf(wv.y, ex2f(fmaf(c3, L2E, nM1)), acc1);
        }

        // quad reduction (lanes 4g..4g+3 share rows)
        acc0 += __shfl_xor_sync(0xFFFFFFFFu, acc0, 1);
        acc0 += __shfl_xor_sync(0xFFFFFFFFu, acc0, 2);
        acc1 += __shfl_xor_sync(0xFFFFFFFFu, acc1, 1);
        acc1 += __shfl_xor_sync(0xFFFFFFFFu, acc1, 2);

        if ((lane & 3) == 0) {
            const size_t obase = (size_t)b * SDIM + tile * 128;
            out[obase + r0]     = 0.5f * s_x2[r0]     - M0 - logf(acc0);
            out[obase + r0 + 8] = 0.5f * s_x2[r0 + 8] - M1 - logf(acc1);
        }
    }
}

// ---------------------------------------------------------------------------
extern "C" void kernel_launch(void* const* d_in, const int* in_sizes, int n_in,
                              void* d_out, int out_size) {
    const float* x      = (const float*)d_in[0];   // [256,1024,32]
    const float* logits = (const float*)d_in[1];   // [256,512]
    const float* means  = (const float*)d_in[2];   // [512,32]
    float* out = (float*)d_out;                    // [256,1024]

    prep_kernel<<<BDIM, KDIM>>>(logits, means);
    nll_hmma<<<BDIM * 2, 256>>>(x, out);
}

// round 13
// speedup vs baseline: 1.0385x; 1.0385x over previous
#include <cuda_runtime.h>
#include <cuda_bf16.h>
#include <math.h>
#include <stdint.h>

#define BDIM 256
#define SDIM 1024
#define DDIM 32
#define KDIM 512
// D * (log(STD) + 0.5*log(2*pi)) with STD=1, D=32  -> 16*log(2*pi)
#define LOG_NORM 29.406033062549525f
#define L2E 1.4426950408889634f

// Scratch (device globals; no allocation allowed)
__device__ float g_w[BDIM * KDIM];   // w'[b,k] = exp(c[b,k] - maxc[b])  in (0,1]
__device__ float g_maxc[BDIM];       // max_k c[b,k]
__device__ float g_maxmu;            // max_k ||mu_k||
// means*L2E in fragment order: [ntile(64)][lane(32)] -> uint4{s0b0,s0b1,s1b0,s1b1}
__device__ uint4 g_bfrag[64 * 32];

__device__ __forceinline__ uint32_t pack_bf16x2(float lo, float hi) {
    uint32_t l = (uint32_t)__bfloat16_as_ushort(__float2bfloat16_rn(lo));
    uint32_t h = (uint32_t)__bfloat16_as_ushort(__float2bfloat16_rn(hi));
    return (h << 16) | l;
}

// pack two fp32 -> f16x2 (lo -> low half)
__device__ __forceinline__ uint32_t pack_f16x2(float lo, float hi) {
    uint32_t r;
    asm("cvt.rn.f16x2.f32 %0, %1, %2;" : "=r"(r) : "f"(hi), "f"(lo));
    return r;
}

__device__ __forceinline__ uint32_t ex2_h2(uint32_t u) {
    uint32_t r;
    asm("ex2.approx.f16x2 %0, %1;" : "=r"(r) : "r"(u));
    return r;
}

__device__ __forceinline__ float2 unpack_h2(uint32_t u) {
    float lo, hi;
    asm("{.reg .f16 l,h; mov.b32 {l,h}, %2; cvt.f32.f16 %0, l; cvt.f32.f16 %1, h;}"
        : "=f"(lo), "=f"(hi) : "r"(u));
    return make_float2(lo, hi);
}

// m16n8k16 bf16 MMA, f32 accumulate (sm_80+ PTX)
__device__ __forceinline__ void mma16816(float& c0, float& c1, float& c2, float& c3,
                                         uint32_t a0, uint32_t a1, uint32_t a2, uint32_t a3,
                                         uint32_t b0, uint32_t b1) {
    asm volatile(
        "mma.sync.aligned.m16n8k16.row.col.f32.bf16.bf16.f32 "
        "{%0,%1,%2,%3}, {%4,%5,%6,%7}, {%8,%9}, {%0,%1,%2,%3};"
        : "+f"(c0), "+f"(c1), "+f"(c2), "+f"(c3)
        : "r"(a0), "r"(a1), "r"(a2), "r"(a3), "r"(b0), "r"(b1));
}

__device__ __forceinline__ float warp_max(float v) {
    #pragma unroll
    for (int o = 16; o > 0; o >>= 1) v = fmaxf(v, __shfl_xor_sync(0xFFFFFFFFu, v, o));
    return v;
}
__device__ __forceinline__ float warp_sum(float v) {
    #pragma unroll
    for (int o = 16; o > 0; o >>= 1) v += __shfl_xor_sync(0xFFFFFFFFu, v, o);
    return v;
}

// ---------------------------------------------------------------------------
// Kernel A: per-batch preprocessing. Grid = B blocks, 512 threads (one per k).
// Writes w' = exp(c - maxc) (so the hot-loop exp argument excludes maxc and
// stays in fp16 range). Blocks 0-7 also build the L2E-prescaled fragment table.
// ---------------------------------------------------------------------------
__global__ void prep_kernel(const float* __restrict__ logits,
                            const float* __restrict__ means) {
    __shared__ float red[16];
    __shared__ float bcast;
    const int b = blockIdx.x;
    const int k = threadIdx.x;
    const int wid = k >> 5;
    const int lane = k & 31;

    // ---- folded frag build: entry e = j*32 + lane_slot ----
    if (blockIdx.x < 8 && k < 256) {
        const int e = blockIdx.x * 256 + k;         // 0..2047
        const int l = e & 31;
        const int j = e >> 5;                       // ntile 0..63
        const int n = j * 8 + (l >> 2);
        const int kb = (l & 3) * 2;
        const float* mp = means + n * DDIM;
        uint4 f;
        f.x = pack_bf16x2(mp[kb]      * L2E, mp[kb + 1]      * L2E);
        f.y = pack_bf16x2(mp[kb + 8]  * L2E, mp[kb + 9]      * L2E);
        f.z = pack_bf16x2(mp[16 + kb] * L2E, mp[16 + kb + 1] * L2E);
        f.w = pack_bf16x2(mp[24 + kb] * L2E, mp[24 + kb + 1] * L2E);
        g_bfrag[e] = f;
    }

    const float lg = logits[b * KDIM + k];

    // ---- max of logits ----
    float v = warp_max(lg);
    if (lane == 0) red[wid] = v;
    __syncthreads();
    if (k == 0) {
        float m = red[0];
        #pragma unroll
        for (int i = 1; i < 16; i++) m = fmaxf(m, red[i]);
        bcast = m;
    }
    __syncthreads();
    const float maxl = bcast;
    __syncthreads();

    // ---- sum of exp ----
    v = warp_sum(__expf(lg - maxl));
    if (lane == 0) red[wid] = v;
    __syncthreads();
    if (k == 0) {
        float s = red[0];
        #pragma unroll
        for (int i = 1; i < 16; i++) s += red[i];
        bcast = maxl + logf(s);
    }
    __syncthreads();
    const float lse = bcast;
    __syncthreads();

    // ---- m2[k] ----
    const float4* mr = (const float4*)(means + (size_t)k * DDIM);
    float m2 = 0.0f;
    #pragma unroll
    for (int i = 0; i < DDIM / 4; i++) {
        float4 q = mr[i];
        m2 += q.x * q.x + q.y * q.y + q.z * q.z + q.w * q.w;
    }

    const float c = lg - lse - 0.5f * m2 - LOG_NORM;

    // ---- max of c (needed BEFORE writing w') ----
    v = warp_max(c);
    if (lane == 0) red[wid] = v;
    __syncthreads();
    if (k == 0) {
        float m = red[0];
        #pragma unroll
        for (int i = 1; i < 16; i++) m = fmaxf(m, red[i]);
        g_maxc[b] = m;
        bcast = m;
    }
    __syncthreads();
    const float maxc = bcast;

    g_w[b * KDIM + k] = expf(c - maxc);             // in (0, 1]
    __syncthreads();

    // ---- max of m2 -> maxmu (same value from every block; benign) ----
    v = warp_max(m2);
    if (lane == 0) red[wid] = v;
    __syncthreads();
    if (k == 0) {
        float m = red[0];
        #pragma unroll
        for (int i = 1; i < 16; i++) m = fmaxf(m, red[i]);
        g_maxmu = sqrtf(m);
    }
}

// ---------------------------------------------------------------------------
// Kernel B: mma.sync GEMM + fused logsumexp epilogue (f16x2 exp).
// MMA emits arg = (dot - xm)*log2e directly (means prescaled by log2e,
// accumulator biased with -xm*log2e). Cauchy-Schwarz: dot <= xm, so
// arg in [-2*xm*log2e, 0] -- safely inside fp16 range.
// CTA = 2 s-tiles (256 rows) of one b. Grid = B * 4 = 1024 CTAs, 256 threads.
// ---------------------------------------------------------------------------
#define PITCH 36    // bf16 elems per staged x row (72 B) -> conflict-dodging pitch
#define TILES 2

__global__ __launch_bounds__(256) void nll_hmma(const float* __restrict__ x,
                                                float* __restrict__ out) {
    __shared__ float s_w[KDIM];                     // 2 KB
    __shared__ float s_xm[128];                     // per-row xm = ||x||*maxmu
    __shared__ float s_x2[128];
    __shared__ __nv_bfloat16 s_xbf[128 * PITCH];    // 9216 B
    __shared__ uint4 s_bf[64 * 32];                 // 32 KB

    const int tid = threadIdx.x;
    const int wid = tid >> 5;
    const int lane = tid & 31;
    const int b = blockIdx.x >> 2;
    const int qsel = blockIdx.x & 3;                // tiles qsel*2 .. +1

    // ---- prologue (once per CTA) ----
    s_w[tid]       = g_w[b * KDIM + tid];
    s_w[tid + 256] = g_w[b * KDIM + tid + 256];
    {
        const uint4* src = (const uint4*)g_bfrag;   // 2048 uint4
        uint4* dst = s_bf;
        #pragma unroll
        for (int i = 0; i < 8; i++) dst[tid + i * 256] = src[tid + i * 256];
    }
    const float maxc = g_maxc[b];
    const float maxmu = g_maxmu;

    const int r0 = wid * 16 + (lane >> 2);
    const int kq = (lane & 3) * 2;

    #pragma unroll 1
    for (int t = 0; t < TILES; t++) {
        const int tile = qsel * TILES + t;
        __syncthreads();                            // s_xbf free (and prologue visible)

        if (tid < 128) {
            const float4* xr =
                (const float4*)(x + ((size_t)b * SDIM + tile * 128 + tid) * DDIM);
            float x2 = 0.0f;
            #pragma unroll
            for (int i = 0; i < 8; i++) {
                float4 vv = xr[i];
                x2 += vv.x * vv.x + vv.y * vv.y + vv.z * vv.z + vv.w * vv.w;
                uint32_t p0 = pack_bf16x2(vv.x, vv.y);
                uint32_t p1 = pack_bf16x2(vv.z, vv.w);
                uint32_t* dp = (uint32_t*)&s_xbf[tid * PITCH + i * 4];
                dp[0] = p0;
                dp[1] = p1;
            }
            s_x2[tid] = x2;
            s_xm[tid] = sqrtf(x2) * maxmu;          // xm only (maxc folded into w')
        }
        __syncthreads();

        // ---- A fragments: rows r0, r0+8, 2 k-steps (x NOT prescaled) ----
        uint32_t a[8];
        #pragma unroll
        for (int s = 0; s < 2; s++) {
            const int kb = s * 16 + kq;
            a[s * 4 + 0] = *(const uint32_t*)&s_xbf[r0 * PITCH + kb];
            a[s * 4 + 1] = *(const uint32_t*)&s_xbf[(r0 + 8) * PITCH + kb];
            a[s * 4 + 2] = *(const uint32_t*)&s_xbf[r0 * PITCH + kb + 8];
            a[s * 4 + 3] = *(const uint32_t*)&s_xbf[(r0 + 8) * PITCH + kb + 8];
        }

        const float xm0 = s_xm[r0];
        const float xm1 = s_xm[r0 + 8];
        const float nM0 = -xm0 * L2E;
        const float nM1 = -xm1 * L2E;
        float acc0 = 0.0f, acc1 = 0.0f;

        #pragma unroll 4
        for (int j = 0; j < 64; j++) {
            const uint4 bf = s_bf[j * 32 + lane];
            float c0 = nM0, c1 = nM0, c2 = nM1, c3 = nM1;
            mma16816(c0, c1, c2, c3, a[0], a[1], a[2], a[3], bf.x, bf.y);
            mma16816(c0, c1, c2, c3, a[4], a[5], a[6], a[7], bf.z, bf.w);
            // c = (dot - xm)*log2e in [-7.3, 0]  ->  exp pairs via f16x2 MUFU
            const float2 e01 = unpack_h2(ex2_h2(pack_f16x2(c0, c1)));
            const float2 e23 = unpack_h2(ex2_h2(pack_f16x2(c2, c3)));
            const float2 wv = *(const float2*)&s_w[j * 8 + kq];
            acc0 = fmaf(wv.x, e01.x, acc0);
            acc0 = fmaf(wv.y, e01.y, acc0);
            acc1 = fmaf(wv.x, e23.x, acc1);
            acc1 = fmaf(wv.y, e23.y, acc1);
        }

        // quad reduction (lanes 4g..4g+3 share rows)
        acc0 += __shfl_xor_sync(0xFFFFFFFFu, acc0, 1);
        acc0 += __shfl_xor_sync(0xFFFFFFFFu, acc0, 2);
        acc1 += __shfl_xor_sync(0xFFFFFFFFu, acc1, 1);
        acc1 += __shfl_xor_sync(0xFFFFFFFFu, acc1, 2);

        if ((lane & 3) == 0) {
            const size_t obase = (size_t)b * SDIM + tile * 128;
            out[obase + r0]     = 0.5f * s_x2[r0]     - maxc - xm0 - logf(acc0);
            out[obase + r0 + 8] = 0.5f * s_x2[r0 + 8] - maxc - xm1 - logf(acc1);
        }
    }
}

// ---------------------------------------------------------------------------
extern "C" void kernel_launch(void* const* d_in, const int* in_sizes, int n_in,
                              void* d_out, int out_size) {
    const float* x      = (const float*)d_in[0];   // [256,1024,32]
    const float* logits = (const float*)d_in[1];   // [256,512]
    const float* means  = (const float*)d_in[2];   // [512,32]
    float* out = (float*)d_out;                    // [256,1024]

    prep_kernel<<<BDIM, KDIM>>>(logits, means);
    nll_hmma<<<BDIM * 4, 256>>>(x, out);
}

// round 15
// speedup vs baseline: 1.2892x; 1.2414x over previous
#include <cuda_runtime.h>
#include <cuda_bf16.h>
#include <math.h>
#include <stdint.h>

#define BDIM 256
#define SDIM 1024
#define DDIM 32
#define KDIM 512
// D * (log(STD) + 0.5*log(2*pi)) with STD=1, D=32  -> 16*log(2*pi)
#define LOG_NORM 29.406033062549525f
#define L2E 1.4426950408889634f

// Scratch (device globals; no allocation allowed)
__device__ uint32_t g_wh[BDIM * 256];  // f16x2-packed w' pairs: (w[2q], w[2q+1])
__device__ float g_maxc[BDIM];         // max_k c[b,k]
__device__ float g_maxmu;              // max_k ||mu_k||
// means*L2E in fragment order: [ntile(64)][lane(32)] -> uint4{s0b0,s0b1,s1b0,s1b1}
__device__ uint4 g_bfrag[64 * 32];

__device__ __forceinline__ uint32_t pack_bf16x2(float lo, float hi) {
    uint32_t l = (uint32_t)__bfloat16_as_ushort(__float2bfloat16_rn(lo));
    uint32_t h = (uint32_t)__bfloat16_as_ushort(__float2bfloat16_rn(hi));
    return (h << 16) | l;
}

// pack two fp32 -> f16x2 (lo -> low half)
__device__ __forceinline__ uint32_t pack_f16x2(float lo, float hi) {
    uint32_t r;
    asm("cvt.rn.f16x2.f32 %0, %1, %2;" : "=r"(r) : "f"(hi), "f"(lo));
    return r;
}

__device__ __forceinline__ uint32_t ex2_h2(uint32_t u) {
    uint32_t r;
    asm("ex2.approx.f16x2 %0, %1;" : "=r"(r) : "r"(u));
    return r;
}

__device__ __forceinline__ uint32_t hfma2(uint32_t a, uint32_t b, uint32_t c) {
    uint32_t d;
    asm("fma.rn.f16x2 %0, %1, %2, %3;" : "=r"(d) : "r"(a), "r"(b), "r"(c));
    return d;
}

__device__ __forceinline__ float2 unpack_h2(uint32_t u) {
    float lo, hi;
    asm("{.reg .f16 l,h; mov.b32 {l,h}, %2; cvt.f32.f16 %0, l; cvt.f32.f16 %1, h;}"
        : "=f"(lo), "=f"(hi) : "r"(u));
    return make_float2(lo, hi);
}

// m16n8k16 bf16 MMA, f32 accumulate (sm_80+ PTX)
__device__ __forceinline__ void mma16816(float& c0, float& c1, float& c2, float& c3,
                                         uint32_t a0, uint32_t a1, uint32_t a2, uint32_t a3,
                                         uint32_t b0, uint32_t b1) {
    asm volatile(
        "mma.sync.aligned.m16n8k16.row.col.f32.bf16.bf16.f32 "
        "{%0,%1,%2,%3}, {%4,%5,%6,%7}, {%8,%9}, {%0,%1,%2,%3};"
        : "+f"(c0), "+f"(c1), "+f"(c2), "+f"(c3)
        : "r"(a0), "r"(a1), "r"(a2), "r"(a3), "r"(b0), "r"(b1));
}

__device__ __forceinline__ float warp_max(float v) {
    #pragma unroll
    for (int o = 16; o > 0; o >>= 1) v = fmaxf(v, __shfl_xor_sync(0xFFFFFFFFu, v, o));
    return v;
}
__device__ __forceinline__ float warp_sum(float v) {
    #pragma unroll
    for (int o = 16; o > 0; o >>= 1) v += __shfl_xor_sync(0xFFFFFFFFu, v, o);
    return v;
}

// ---------------------------------------------------------------------------
// Kernel A: per-batch preprocessing. Grid = B blocks, 512 threads (one per k).
// Writes f16x2-packed w' = exp(c - maxc) pairs. Blocks 0-7 also build the
// L2E-prescaled fragment table.
// ---------------------------------------------------------------------------
__global__ void prep_kernel(const float* __restrict__ logits,
                            const float* __restrict__ means) {
    __shared__ float red[16];
    __shared__ float bcast;
    const int b = blockIdx.x;
    const int k = threadIdx.x;
    const int wid = k >> 5;
    const int lane = k & 31;

    // ---- folded frag build: entry e = j*32 + lane_slot ----
    if (blockIdx.x < 8 && k < 256) {
        const int e = blockIdx.x * 256 + k;         // 0..2047
        const int l = e & 31;
        const int j = e >> 5;                       // ntile 0..63
        const int n = j * 8 + (l >> 2);
        const int kb = (l & 3) * 2;
        const float* mp = means + n * DDIM;
        uint4 f;
        f.x = pack_bf16x2(mp[kb]      * L2E, mp[kb + 1]      * L2E);
        f.y = pack_bf16x2(mp[kb + 8]  * L2E, mp[kb + 9]      * L2E);
        f.z = pack_bf16x2(mp[16 + kb] * L2E, mp[16 + kb + 1] * L2E);
        f.w = pack_bf16x2(mp[24 + kb] * L2E, mp[24 + kb + 1] * L2E);
        g_bfrag[e] = f;
    }

    const float lg = logits[b * KDIM + k];

    // ---- max of logits ----
    float v = warp_max(lg);
    if (lane == 0) red[wid] = v;
    __syncthreads();
    if (k == 0) {
        float m = red[0];
        #pragma unroll
        for (int i = 1; i < 16; i++) m = fmaxf(m, red[i]);
        bcast = m;
    }
    __syncthreads();
    const float maxl = bcast;
    __syncthreads();

    // ---- sum of exp ----
    v = warp_sum(__expf(lg - maxl));
    if (lane == 0) red[wid] = v;
    __syncthreads();
    if (k == 0) {
        float s = red[0];
        #pragma unroll
        for (int i = 1; i < 16; i++) s += red[i];
        bcast = maxl + logf(s);
    }
    __syncthreads();
    const float lse = bcast;
    __syncthreads();

    // ---- m2[k] ----
    const float4* mr = (const float4*)(means + (size_t)k * DDIM);
    float m2 = 0.0f;
    #pragma unroll
    for (int i = 0; i < DDIM / 4; i++) {
        float4 q = mr[i];
        m2 += q.x * q.x + q.y * q.y + q.z * q.z + q.w * q.w;
    }

    const float c = lg - lse - 0.5f * m2 - LOG_NORM;

    // ---- max of c (needed BEFORE writing w') ----
    v = warp_max(c);
    if (lane == 0) red[wid] = v;
    __syncthreads();
    if (k == 0) {
        float m = red[0];
        #pragma unroll
        for (int i = 1; i < 16; i++) m = fmaxf(m, red[i]);
        g_maxc[b] = m;
        bcast = m;
    }
    __syncthreads();
    const float maxc = bcast;

    // w' in (0,1]; pack adjacent pairs to f16x2 (even k writes)
    {
        const float wv = expf(c - maxc);
        const float wnext = __shfl_down_sync(0xFFFFFFFFu, wv, 1);
        if (!(k & 1)) g_wh[b * 256 + (k >> 1)] = pack_f16x2(wv, wnext);
    }
    __syncthreads();

    // ---- max of m2 -> maxmu (same value from every block; benign) ----
    v = warp_max(m2);
    if (lane == 0) red[wid] = v;
    __syncthreads();
    if (k == 0) {
        float m = red[0];
        #pragma unroll
        for (int i = 1; i < 16; i++) m = fmaxf(m, red[i]);
        g_maxmu = sqrtf(m);
    }
}

// ---------------------------------------------------------------------------
// Kernel B: mma.sync GEMM + fused logsumexp epilogue, fully-packed fp16 path.
// CTA = 256 s-rows (2 MMA tiles) of one b, processed in ONE j-loop: each
// B-fragment LDS.128 feeds 4 MMAs (2 tiles x 2 k-steps). Accumulation in
// f16x2 via HFMA2, widened to fp32 every 8 j. Exp arg = (dot - xm)*log2e
// emitted directly by the MMA (prescaled means, biased accumulator init);
// Cauchy-Schwarz bounds it in [-2*xm*log2e, 0] -- inside fp16 range.
// Grid = B * 4 = 1024 CTAs, 256 threads.
// ---------------------------------------------------------------------------
#define PITCH 36    // bf16 elems per staged x row (72 B) -> conflict-dodging pitch

// dynamic smem layout (bytes)
#define SM_WH   0                       // 256 u32
#define SM_X2   1024                    // 256 f
#define SM_XM   2048                    // 256 f
#define SM_XBF  3072                    // 256 * 72 B = 18432
#define SM_BF   21504                   // 2048 uint4 = 32768
#define SM_TOTAL 54272

__global__ __launch_bounds__(256) void nll_hmma(const float* __restrict__ x,
                                                float* __restrict__ out) {
    extern __shared__ char smem[];
    uint32_t* s_wh = (uint32_t*)(smem + SM_WH);
    float* s_x2 = (float*)(smem + SM_X2);
    float* s_xm = (float*)(smem + SM_XM);
    __nv_bfloat16* s_xbf = (__nv_bfloat16*)(smem + SM_XBF);
    uint4* s_bf = (uint4*)(smem + SM_BF);

    const int tid = threadIdx.x;
    const int wid = tid >> 5;
    const int lane = tid & 31;
    const int b = blockIdx.x >> 2;
    const int qsel = blockIdx.x & 3;                // rows qsel*256 .. +255

    // ---- prologue ----
    s_wh[tid] = g_wh[b * 256 + tid];
    {
        const uint4* src = (const uint4*)g_bfrag;   // 2048 uint4
        #pragma unroll
        for (int i = 0; i < 8; i++) s_bf[tid + i * 256] = src[tid + i * 256];
    }
    const float maxc = g_maxc[b];
    const float maxmu = g_maxmu;

    // ---- stage x: thread tid stages row tid (covers both 128-row tiles) ----
    {
        const float4* xr =
            (const float4*)(x + ((size_t)b * SDIM + qsel * 256 + tid) * DDIM);
        float x2 = 0.0f;
        #pragma unroll
        for (int i = 0; i < 8; i++) {
            float4 vv = xr[i];
            x2 += vv.x * vv.x + vv.y * vv.y + vv.z * vv.z + vv.w * vv.w;
            uint32_t p0 = pack_bf16x2(vv.x, vv.y);
            uint32_t p1 = pack_bf16x2(vv.z, vv.w);
            uint32_t* dp = (uint32_t*)&s_xbf[tid * PITCH + i * 4];
            dp[0] = p0;
            dp[1] = p1;
        }
        s_x2[tid] = x2;
        s_xm[tid] = sqrtf(x2) * maxmu;
    }
    __syncthreads();

    // ---- A fragments for both tiles: rows r0, r0+8 (tile0) / +128 (tile1) ----
    const int r0 = wid * 16 + (lane >> 2);
    const int kq = (lane & 3) * 2;
    uint32_t a0[8], a1[8];
    #pragma unroll
    for (int s = 0; s < 2; s++) {
        const int kb = s * 16 + kq;
        a0[s * 4 + 0] = *(const uint32_t*)&s_xbf[r0 * PITCH + kb];
        a0[s * 4 + 1] = *(const uint32_t*)&s_xbf[(r0 + 8) * PITCH + kb];
        a0[s * 4 + 2] = *(const uint32_t*)&s_xbf[r0 * PITCH + kb + 8];
        a0[s * 4 + 3] = *(const uint32_t*)&s_xbf[(r0 + 8) * PITCH + kb + 8];
        a1[s * 4 + 0] = *(const uint32_t*)&s_xbf[(r0 + 128) * PITCH + kb];
        a1[s * 4 + 1] = *(const uint32_t*)&s_xbf[(r0 + 136) * PITCH + kb];
        a1[s * 4 + 2] = *(const uint32_t*)&s_xbf[(r0 + 128) * PITCH + kb + 8];
        a1[s * 4 + 3] = *(const uint32_t*)&s_xbf[(r0 + 136) * PITCH + kb + 8];
    }

    const float xm0 = s_xm[r0];
    const float xm1 = s_xm[r0 + 8];
    const float xm2 = s_xm[r0 + 128];
    const float xm3 = s_xm[r0 + 136];
    const float nM0 = -xm0 * L2E;
    const float nM1 = -xm1 * L2E;
    const float nM2 = -xm2 * L2E;
    const float nM3 = -xm3 * L2E;

    float f0 = 0.0f, f1 = 0.0f, f2v = 0.0f, f3 = 0.0f;

    #pragma unroll 1
    for (int jo = 0; jo < 8; jo++) {
        uint32_t h0 = 0u, h1 = 0u, h2 = 0u, h3 = 0u;
        #pragma unroll
        for (int ji = 0; ji < 8; ji++) {
            const int j = jo * 8 + ji;
            const uint4 bf = s_bf[j * 32 + lane];
            float c0 = nM0, c1 = nM0, c2 = nM1, c3 = nM1;
            mma16816(c0, c1, c2, c3, a0[0], a0[1], a0[2], a0[3], bf.x, bf.y);
            mma16816(c0, c1, c2, c3, a0[4], a0[5], a0[6], a0[7], bf.z, bf.w);
            float c4 = nM2, c5 = nM2, c6 = nM3, c7 = nM3;
            mma16816(c4, c5, c6, c7, a1[0], a1[1], a1[2], a1[3], bf.x, bf.y);
            mma16816(c4, c5, c6, c7, a1[4], a1[5], a1[6], a1[7], bf.z, bf.w);
            const uint32_t wq = s_wh[j * 4 + (lane & 3)];
            h0 = hfma2(wq, ex2_h2(pack_f16x2(c0, c1)), h0);
            h1 = hfma2(wq, ex2_h2(pack_f16x2(c2, c3)), h1);
            h2 = hfma2(wq, ex2_h2(pack_f16x2(c4, c5)), h2);
            h3 = hfma2(wq, ex2_h2(pack_f16x2(c6, c7)), h3);
        }
        // widen (both halves of each accumulator belong to the same row sum)
        const float2 u0 = unpack_h2(h0);
        const float2 u1 = unpack_h2(h1);
        const float2 u2 = unpack_h2(h2);
        const float2 u3 = unpack_h2(h3);
        f0 += u0.x + u0.y;
        f1 += u1.x + u1.y;
        f2v += u2.x + u2.y;
        f3 += u3.x + u3.y;
    }

    // quad reduction (lanes 4g..4g+3 share rows)
    #pragma unroll
    for (int o = 1; o <= 2; o <<= 1) {
        f0 += __shfl_xor_sync(0xFFFFFFFFu, f0, o);
        f1 += __shfl_xor_sync(0xFFFFFFFFu, f1, o);
        f2v += __shfl_xor_sync(0xFFFFFFFFu, f2v, o);
        f3 += __shfl_xor_sync(0xFFFFFFFFu, f3, o);
    }

    if ((lane & 3) == 0) {
        const size_t obase = (size_t)b * SDIM + qsel * 256;
        out[obase + r0]       = 0.5f * s_x2[r0]       - maxc - xm0 - logf(f0);
        out[obase + r0 + 8]   = 0.5f * s_x2[r0 + 8]   - maxc - xm1 - logf(f1);
        out[obase + r0 + 128] = 0.5f * s_x2[r0 + 128] - maxc - xm2 - logf(f2v);
        out[obase + r0 + 136] = 0.5f * s_x2[r0 + 136] - maxc - xm3 - logf(f3);
    }
}

// ---------------------------------------------------------------------------
extern "C" void kernel_launch(void* const* d_in, const int* in_sizes, int n_in,
                              void* d_out, int out_size) {
    const float* x      = (const float*)d_in[0];   // [256,1024,32]
    const float* logits = (const float*)d_in[1];   // [256,512]
    const float* means  = (const float*)d_in[2];   // [512,32]
    float* out = (float*)d_out;                    // [256,1024]

    cudaFuncSetAttribute(nll_hmma, cudaFuncAttributeMaxDynamicSharedMemorySize, SM_TOTAL);

    prep_kernel<<<BDIM, KDIM>>>(logits, means);
    nll_hmma<<<BDIM * 4, 256, SM_TOTAL>>>(x, out);
}